// round 1
// baseline (speedup 1.0000x reference)
#include <cuda_runtime.h>
#include <math.h>

#define B_   32
#define TK_  2048
#define N_   1024
#define M_   (B_ * TK_)   // 65536 rows
#define KTOT 2048         // combined K (h then q_h)

// Scratch (no allocation allowed in kernel_launch)
__device__ float g_dec[B_ * N_];        // dec_feat [B, N]
__device__ float g_part[8 * M_];        // per-n-tile partial score sums [8][M]

// ---------------------------------------------------------------------------
// dec_feat[b][m] = sum_k s_t_hat[b][k] * W_d[m][k] + b_d[m]
// grid (32, 128), 256 threads = 8 warps, warp-per-output-m
// ---------------------------------------------------------------------------
__global__ __launch_bounds__(256) void dec_kernel(
    const float* __restrict__ s_t_hat,
    const float* __restrict__ Wd,
    const float* __restrict__ bd)
{
    int b    = blockIdx.x;
    int warp = threadIdx.x >> 5;
    int lane = threadIdx.x & 31;
    int m    = blockIdx.y * 8 + warp;

    const float* sp = s_t_hat + (size_t)b * N_;
    const float* wp = Wd + (size_t)m * N_;
    float acc = 0.f;
    #pragma unroll 4
    for (int k = lane; k < N_; k += 32) acc = fmaf(sp[k], wp[k], acc);
    #pragma unroll
    for (int o = 16; o > 0; o >>= 1) acc += __shfl_xor_sync(0xffffffffu, acc, o);
    if (lane == 0) g_dec[(size_t)b * N_ + m] = acc + bd[m];
}

// ---------------------------------------------------------------------------
// scores: fused GEMM  C[m][n] = h[m]·W_h[n] + q[m]·W_q[n]   (K = 2048 total)
// epilogue: partial[m] (this n-tile) = sum_n tanh(C + dec + cov*W_c) * v_w
// grid (M/128 = 512, N/128 = 8), 256 threads, 8x8 per-thread microtile
// ---------------------------------------------------------------------------
__global__ __launch_bounds__(256) void scores_kernel(
    const float* __restrict__ h,  const float* __restrict__ q,
    const float* __restrict__ Wh, const float* __restrict__ Wq,
    const float* __restrict__ Wc, const float* __restrict__ vw,
    const float* __restrict__ cov)
{
    __shared__ float As[8][128];
    __shared__ float Bs[8][128];
    __shared__ float red[128][16];
    __shared__ float dec_s[128], wc_s[128], vw_s[128], cov_s[128];

    const int tid   = threadIdx.x;
    const int mBase = blockIdx.x * 128;
    const int nBase = blockIdx.y * 128;
    const int b     = mBase >> 11;          // row tile lies within one batch (128 | 2048)
    const int trow  = mBase & (TK_ - 1);

    if (tid < 128) {
        dec_s[tid] = g_dec[(size_t)b * N_ + nBase + tid];
        wc_s[tid]  = Wc[nBase + tid];
        vw_s[tid]  = vw[nBase + tid];
        cov_s[tid] = cov[(size_t)b * TK_ + trow + tid];
    }

    const int lRow = tid >> 1;              // 0..127
    const int lCol = (tid & 1) << 2;        // 0 or 4
    const int ty   = tid >> 4;              // 0..15
    const int tx   = tid & 15;              // 0..15

    const size_t aOff = (size_t)(mBase + lRow) * N_ + lCol;
    const size_t bOff = (size_t)(nBase + lRow) * N_ + lCol;

    float acc[8][8];
    #pragma unroll
    for (int i = 0; i < 8; i++)
        #pragma unroll
        for (int j = 0; j < 8; j++) acc[i][j] = 0.f;

    for (int kb = 0; kb < KTOT; kb += 8) {
        const float* Ap;
        const float* Bp;
        if (kb < N_) { Ap = h + aOff + kb;        Bp = Wh + bOff + kb; }
        else         { Ap = q + aOff + (kb - N_); Bp = Wq + bOff + (kb - N_); }
        float4 av = *(const float4*)Ap;
        float4 bv = *(const float4*)Bp;

        __syncthreads();
        As[lCol + 0][lRow] = av.x; As[lCol + 1][lRow] = av.y;
        As[lCol + 2][lRow] = av.z; As[lCol + 3][lRow] = av.w;
        Bs[lCol + 0][lRow] = bv.x; Bs[lCol + 1][lRow] = bv.y;
        Bs[lCol + 2][lRow] = bv.z; Bs[lCol + 3][lRow] = bv.w;
        __syncthreads();

        #pragma unroll
        for (int k = 0; k < 8; k++) {
            float a[8], bb[8];
            #pragma unroll
            for (int i = 0; i < 8; i++) a[i]  = As[k][ty * 8 + i];
            #pragma unroll
            for (int j = 0; j < 8; j++) bb[j] = Bs[k][tx * 8 + j];
            #pragma unroll
            for (int i = 0; i < 8; i++)
                #pragma unroll
                for (int j = 0; j < 8; j++)
                    acc[i][j] = fmaf(a[i], bb[j], acc[i][j]);
        }
    }

    // fused epilogue: tanh + dot with v_w, reduce across the 16 column-threads
    #pragma unroll
    for (int i = 0; i < 8; i++) {
        const int r = ty * 8 + i;
        float s = 0.f;
        #pragma unroll
        for (int j = 0; j < 8; j++) {
            const int c = tx * 8 + j;
            float v = tanhf(acc[i][j] + dec_s[c] + cov_s[r] * wc_s[c]) * vw_s[c];
            s += v;
        }
        red[r][tx] = s;
    }
    __syncthreads();
    if (tid < 128) {
        float s = 0.f;
        #pragma unroll
        for (int x = 0; x < 16; x++) s += red[tid][x];
        g_part[(size_t)blockIdx.y * M_ + mBase + tid] = s;
    }
}

// ---------------------------------------------------------------------------
// softmax over TK with mask + renormalize (denominator cancels):
//   attn = e^{s-max} * mask / sum(e^{s-max} * mask)
// also writes coverage_out = coverage + attn. grid(32), 256 threads.
// ---------------------------------------------------------------------------
__global__ __launch_bounds__(256) void softmax_kernel(
    const float* __restrict__ mask,
    const float* __restrict__ cov,
    float* __restrict__ out)
{
    __shared__ float sh[TK_];
    __shared__ float red[256];
    const int b = blockIdx.x, tid = threadIdx.x;

    float lmax = -1e30f;
    for (int t = tid; t < TK_; t += 256) {
        float s = 0.f;
        #pragma unroll
        for (int c = 0; c < 8; c++) s += g_part[(size_t)c * M_ + (size_t)b * TK_ + t];
        sh[t] = s;
        lmax = fmaxf(lmax, s);
    }
    red[tid] = lmax; __syncthreads();
    for (int o = 128; o > 0; o >>= 1) {
        if (tid < o) red[tid] = fmaxf(red[tid], red[tid + o]);
        __syncthreads();
    }
    const float mx = red[0];
    __syncthreads();

    float lsum = 0.f;
    for (int t = tid; t < TK_; t += 256) {
        float e = expf(sh[t] - mx) * mask[(size_t)b * TK_ + t];
        sh[t] = e;
        lsum += e;
    }
    red[tid] = lsum; __syncthreads();
    for (int o = 128; o > 0; o >>= 1) {
        if (tid < o) red[tid] += red[tid + o];
        __syncthreads();
    }
    const float inv = 1.f / red[0];

    for (int t = tid; t < TK_; t += 256) {
        float a = sh[t] * inv;
        out[(size_t)B_ * N_ + (size_t)b * TK_ + t]                      = a;               // attn
        out[(size_t)B_ * N_ + (size_t)B_ * TK_ + (size_t)b * TK_ + t]   = cov[(size_t)b * TK_ + t] + a; // coverage_out
    }
}

// ---------------------------------------------------------------------------
// c_t[b][n] = sum_t attn[b][t] * h[b][t][n].  grid (32, 4), 256 threads.
// ---------------------------------------------------------------------------
__global__ __launch_bounds__(256) void ct_kernel(
    const float* __restrict__ h,
    float* __restrict__ out)
{
    __shared__ float ash[256];
    const int b = blockIdx.x;
    const int n = blockIdx.y * 256 + threadIdx.x;
    const float* attn = out + (size_t)B_ * N_ + (size_t)b * TK_;

    float acc = 0.f;
    for (int t0 = 0; t0 < TK_; t0 += 256) {
        __syncthreads();
        ash[threadIdx.x] = attn[t0 + threadIdx.x];
        __syncthreads();
        const float* hp = h + ((size_t)b * TK_ + t0) * N_ + n;
        #pragma unroll 8
        for (int tt = 0; tt < 256; tt++)
            acc = fmaf(ash[tt], hp[(size_t)tt * N_], acc);
    }
    out[(size_t)b * N_ + n] = acc;
}

// ---------------------------------------------------------------------------
extern "C" void kernel_launch(void* const* d_in, const int* in_sizes, int n_in,
                              void* d_out, int out_size)
{
    const float* s_t_hat = (const float*)d_in[0];
    const float* h       = (const float*)d_in[1];
    const float* mask    = (const float*)d_in[2];
    const float* cov     = (const float*)d_in[3];
    const float* q_h     = (const float*)d_in[4];
    const float* Wh      = (const float*)d_in[5];
    const float* Wq      = (const float*)d_in[6];
    const float* Wc      = (const float*)d_in[7];
    const float* Wd      = (const float*)d_in[8];
    const float* bd      = (const float*)d_in[9];
    const float* vw      = (const float*)d_in[10];
    float* out = (float*)d_out;

    dec_kernel<<<dim3(32, 128), 256>>>(s_t_hat, Wd, bd);
    scores_kernel<<<dim3(M_ / 128, N_ / 128), 256>>>(h, q_h, Wh, Wq, Wc, vw, cov);
    softmax_kernel<<<32, 256>>>(mask, cov, out);
    ct_kernel<<<dim3(32, N_ / 256), 256>>>(h, out);
}

// round 4
// speedup vs baseline: 2.9922x; 2.9922x over previous
#include <cuda_runtime.h>
#include <cuda_bf16.h>
#include <math.h>
#include <stdint.h>

#define B_    32
#define TK_   2048
#define N_    1024
#define M_    (B_ * TK_)        // 65536
#define KTOT  2048
#define NPART 8                 // N_/128 column blocks -> score partials

// ---------------- scratch (no allocs allowed) ----------------
__device__ float g_dec[B_ * N_];
__device__ float g_part[NPART * M_];
__device__ float g_ct[8 * B_ * N_];

// ---------------- smem layout (dynamic) ----------------
// bf16 tiles, row stride 40 elements (80B) for conflict-free ldmatrix
#define A_HI 0
#define A_LO 10240
#define B_HI 20480
#define B_LO 30720
#define STAGE_BYTES 40960
#define EPI_DEC (2 * STAGE_BYTES)          // 81920
#define EPI_WC  (EPI_DEC + 512)
#define EPI_VW  (EPI_WC + 512)
#define EPI_COV (EPI_VW + 512)
#define EPI_RED (EPI_COV + 512)            // 128*16 floats = 8192B
#define SMEM_TOTAL (EPI_RED + 8192)        // 92160

__device__ __forceinline__ uint32_t smem_u32(const void* p) {
    uint32_t a;
    asm("{ .reg .u64 t; cvta.to.shared.u64 t, %1; cvt.u32.u64 %0, t; }" : "=r"(a) : "l"(p));
    return a;
}

#define LDSM_X4(r0, r1, r2, r3, addr) \
    asm volatile("ldmatrix.sync.aligned.m8n8.x4.shared.b16 {%0,%1,%2,%3}, [%4];" \
                 : "=r"(r0), "=r"(r1), "=r"(r2), "=r"(r3) : "r"(addr))
#define LDSM_X2(r0, r1, addr) \
    asm volatile("ldmatrix.sync.aligned.m8n8.x2.shared.b16 {%0,%1}, [%2];" \
                 : "=r"(r0), "=r"(r1) : "r"(addr))
#define MMA16816(d, a, b) \
    asm volatile("mma.sync.aligned.m16n8k16.row.col.f32.bf16.bf16.f32 " \
                 "{%0,%1,%2,%3}, {%4,%5,%6,%7}, {%8,%9}, {%0,%1,%2,%3};" \
                 : "+f"((d)[0]), "+f"((d)[1]), "+f"((d)[2]), "+f"((d)[3]) \
                 : "r"((a)[0]), "r"((a)[1]), "r"((a)[2]), "r"((a)[3]), \
                   "r"((b)[0]), "r"((b)[1]))

// ===========================================================================
// dec_feat[b][m] = s_t_hat[b] . W_d[m] + b_d[m]
// ===========================================================================
__global__ __launch_bounds__(256) void dec_kernel(
    const float* __restrict__ s_t_hat,
    const float* __restrict__ Wd,
    const float* __restrict__ bd)
{
    int b    = blockIdx.x;
    int warp = threadIdx.x >> 5;
    int lane = threadIdx.x & 31;
    int m    = blockIdx.y * 8 + warp;

    const float* sp = s_t_hat + (size_t)b * N_;
    const float* wp = Wd + (size_t)m * N_;
    float acc = 0.f;
    #pragma unroll 4
    for (int k = lane; k < N_; k += 32) acc = fmaf(sp[k], wp[k], acc);
    #pragma unroll
    for (int o = 16; o > 0; o >>= 1) acc += __shfl_xor_sync(0xffffffffu, acc, o);
    if (lane == 0) g_dec[(size_t)b * N_ + m] = acc + bd[m];
}

// ===========================================================================
// scores via bf16 mma.sync (3-term split): C = [h|q] @ [Wh|Wq]^T
// fused tanh epilogue -> per-column-block row partials.
// grid (8, 512), 256 threads (8 warps, 2x4 warp grid, 64x32 per warp)
// ===========================================================================
__global__ __launch_bounds__(256, 1) void scores_mma(
    const float* __restrict__ h,  const float* __restrict__ q,
    const float* __restrict__ Wh, const float* __restrict__ Wq,
    const float* __restrict__ Wc, const float* __restrict__ vw,
    const float* __restrict__ cov)
{
    extern __shared__ char sm[];
    const uint32_t smem = smem_u32(sm);
    const int tid  = threadIdx.x;
    const int lane = tid & 31;
    const int wid  = tid >> 5;
    const int wm   = wid & 1;       // 2 m-groups of 64
    const int wn   = wid >> 1;      // 4 n-groups of 32
    const int mBase = blockIdx.y * 128;
    const int nBase = blockIdx.x * 128;
    const int b     = mBase >> 11;          // 128 | 2048 -> tile within one batch
    const int trow  = mBase & (TK_ - 1);

    float* dec_s = (float*)(sm + EPI_DEC);
    float* wc_s  = (float*)(sm + EPI_WC);
    float* vw_s  = (float*)(sm + EPI_VW);
    float* cov_s = (float*)(sm + EPI_COV);
    float* red   = (float*)(sm + EPI_RED);

    if (tid < 128) {
        dec_s[tid] = g_dec[(size_t)b * N_ + nBase + tid];
        wc_s[tid]  = Wc[nBase + tid];
        vw_s[tid]  = vw[nBase + tid];
        cov_s[tid] = cov[(size_t)b * TK_ + trow + tid];
    }

    // ldmatrix lane-address components
    const int g = lane >> 3;
    const uint32_t a_row = (uint32_t)(((g & 1) << 3) + (lane & 7));
    const uint32_t a_col = (uint32_t)((g >> 1) << 3);
    const int l16 = lane & 15;
    const uint32_t b_row = (uint32_t)(l16 & 7);
    const uint32_t b_col = (uint32_t)((l16 >> 3) << 3);

    // loader indices: 4 units each for A and B; unit u covers row u>>3, seg u&7
    int r4[4], s4[4];
    #pragma unroll
    for (int j = 0; j < 4; j++) {
        int u = tid + 256 * j;
        r4[j] = u >> 3;
        s4[j] = u & 7;
    }

    float acc[4][4][4];
    #pragma unroll
    for (int mf = 0; mf < 4; mf++)
        #pragma unroll
        for (int nf = 0; nf < 4; nf++)
            #pragma unroll
            for (int x = 0; x < 4; x++) acc[mf][nf][x] = 0.f;

    float4 rv[8];

    auto load_step = [&](int ks) {
        const int k = ks * 32;
        const float *pA, *pB;
        if (k < 1024) { pA = h + (size_t)mBase * N_ + k;          pB = Wh + (size_t)nBase * N_ + k; }
        else          { pA = q + (size_t)mBase * N_ + (k - 1024); pB = Wq + (size_t)nBase * N_ + (k - 1024); }
        #pragma unroll
        for (int j = 0; j < 4; j++)
            rv[j] = *(const float4*)(pA + (size_t)r4[j] * N_ + s4[j] * 4);
        #pragma unroll
        for (int j = 0; j < 4; j++)
            rv[4 + j] = *(const float4*)(pB + (size_t)r4[j] * N_ + s4[j] * 4);
    };

    auto store_step = [&](int st) {
        char* base = sm + (size_t)st * STAGE_BYTES;
        #pragma unroll
        for (int j = 0; j < 8; j++) {
            float4 v = rv[j];
            uint32_t hi01, hi23, lo01, lo23;
            asm("cvt.rn.bf16x2.f32 %0, %1, %2;" : "=r"(hi01) : "f"(v.y), "f"(v.x));
            asm("cvt.rn.bf16x2.f32 %0, %1, %2;" : "=r"(hi23) : "f"(v.w), "f"(v.z));
            float rx = v.x - __uint_as_float(hi01 << 16);
            float ry = v.y - __uint_as_float(hi01 & 0xffff0000u);
            float rz = v.z - __uint_as_float(hi23 << 16);
            float rw = v.w - __uint_as_float(hi23 & 0xffff0000u);
            asm("cvt.rn.bf16x2.f32 %0, %1, %2;" : "=r"(lo01) : "f"(ry), "f"(rx));
            asm("cvt.rn.bf16x2.f32 %0, %1, %2;" : "=r"(lo23) : "f"(rw), "f"(rz));

            const int jj = j & 3;
            uint32_t off = (uint32_t)(r4[jj] * 80 + s4[jj] * 8);
            char* bh = base + (j < 4 ? A_HI : B_HI);
            char* bl = base + (j < 4 ? A_LO : B_LO);
            *(uint2*)(bh + off) = make_uint2(hi01, hi23);
            *(uint2*)(bl + off) = make_uint2(lo01, lo23);
        }
    };

    auto mma_step = [&](int st) {
        const uint32_t Ahi = smem + st * STAGE_BYTES + A_HI;
        const uint32_t Alo = smem + st * STAGE_BYTES + A_LO;
        const uint32_t Bhi = smem + st * STAGE_BYTES + B_HI;
        const uint32_t Blo = smem + st * STAGE_BYTES + B_LO;
        #pragma unroll
        for (int kf = 0; kf < 2; kf++) {
            uint32_t ah[4][4], al[4][4], bh[4][2], bl[4][2];
            #pragma unroll
            for (int mf = 0; mf < 4; mf++) {
                uint32_t off = (uint32_t)((wm * 64 + mf * 16 + a_row) * 80 + (kf * 16 + a_col) * 2);
                LDSM_X4(ah[mf][0], ah[mf][1], ah[mf][2], ah[mf][3], Ahi + off);
                LDSM_X4(al[mf][0], al[mf][1], al[mf][2], al[mf][3], Alo + off);
            }
            #pragma unroll
            for (int nf = 0; nf < 4; nf++) {
                uint32_t off = (uint32_t)((wn * 32 + nf * 8 + b_row) * 80 + (kf * 16 + b_col) * 2);
                LDSM_X2(bh[nf][0], bh[nf][1], Bhi + off);
                LDSM_X2(bl[nf][0], bl[nf][1], Blo + off);
            }
            #pragma unroll
            for (int mf = 0; mf < 4; mf++)
                #pragma unroll
                for (int nf = 0; nf < 4; nf++) {
                    MMA16816(acc[mf][nf], ah[mf], bh[nf]);
                    MMA16816(acc[mf][nf], ah[mf], bl[nf]);
                    MMA16816(acc[mf][nf], al[mf], bh[nf]);
                }
        }
    };

    // prologue
    load_step(0);
    store_step(0);
    __syncthreads();

    for (int ks = 0; ks < KTOT / 32; ++ks) {
        const int cur = ks & 1;
        if (ks + 1 < KTOT / 32) load_step(ks + 1);
        mma_step(cur);
        if (ks + 1 < KTOT / 32) store_step(cur ^ 1);
        __syncthreads();
    }

    // fused epilogue: tanh + dot with v_w, per-row partials
    #pragma unroll
    for (int mf = 0; mf < 4; mf++) {
        const int rA = wm * 64 + mf * 16 + (lane >> 2);
        const int rB = rA + 8;
        const float covA = cov_s[rA];
        const float covB = cov_s[rB];
        float sA = 0.f, sB = 0.f;
        #pragma unroll
        for (int nf = 0; nf < 4; nf++) {
            const int n0 = wn * 32 + nf * 8 + ((lane & 3) << 1);
            const float d0 = dec_s[n0],   d1 = dec_s[n0 + 1];
            const float w0 = wc_s[n0],    w1 = wc_s[n0 + 1];
            const float v0 = vw_s[n0],    v1 = vw_s[n0 + 1];
            sA += tanhf(acc[mf][nf][0] + d0 + covA * w0) * v0
                + tanhf(acc[mf][nf][1] + d1 + covA * w1) * v1;
            sB += tanhf(acc[mf][nf][2] + d0 + covB * w0) * v0
                + tanhf(acc[mf][nf][3] + d1 + covB * w1) * v1;
        }
        const int colslot = wn * 4 + (lane & 3);
        red[rA * 16 + colslot] = sA;
        red[rB * 16 + colslot] = sB;
    }
    __syncthreads();
    if (tid < 128) {
        float s = 0.f;
        #pragma unroll
        for (int x = 0; x < 16; x++) s += red[tid * 16 + x];
        g_part[(size_t)blockIdx.x * M_ + mBase + tid] = s;
    }
}

// ===========================================================================
// softmax with mask + renormalize; writes attn and coverage_out
// ===========================================================================
__global__ __launch_bounds__(256) void softmax_kernel(
    const float* __restrict__ mask,
    const float* __restrict__ cov,
    float* __restrict__ out)
{
    __shared__ float sh[TK_];
    __shared__ float red[256];
    const int b = blockIdx.x, tid = threadIdx.x;

    float lmax = -1e30f;
    for (int t = tid; t < TK_; t += 256) {
        float s = 0.f;
        #pragma unroll
        for (int c = 0; c < NPART; c++) s += g_part[(size_t)c * M_ + (size_t)b * TK_ + t];
        sh[t] = s;
        lmax = fmaxf(lmax, s);
    }
    red[tid] = lmax; __syncthreads();
    for (int o = 128; o > 0; o >>= 1) {
        if (tid < o) red[tid] = fmaxf(red[tid], red[tid + o]);
        __syncthreads();
    }
    const float mx = red[0];
    __syncthreads();

    float lsum = 0.f;
    for (int t = tid; t < TK_; t += 256) {
        float e = expf(sh[t] - mx) * mask[(size_t)b * TK_ + t];
        sh[t] = e;
        lsum += e;
    }
    red[tid] = lsum; __syncthreads();
    for (int o = 128; o > 0; o >>= 1) {
        if (tid < o) red[tid] += red[tid + o];
        __syncthreads();
    }
    const float inv = 1.f / red[0];

    for (int t = tid; t < TK_; t += 256) {
        float a = sh[t] * inv;
        out[(size_t)B_ * N_ + (size_t)b * TK_ + t] = a;
        out[(size_t)B_ * N_ + (size_t)B_ * TK_ + (size_t)b * TK_ + t] =
            cov[(size_t)b * TK_ + t] + a;
    }
}

// ===========================================================================
// c_t partials over 8 T-chunks, then reduce
// ===========================================================================
__global__ __launch_bounds__(256) void ct_part_kernel(
    const float* __restrict__ h,
    const float* __restrict__ out)
{
    __shared__ float ash[256];
    const int b = blockIdx.x;
    const int n = blockIdx.y * 256 + threadIdx.x;
    const int z = blockIdx.z;
    const float* attn = out + (size_t)B_ * N_ + (size_t)b * TK_ + z * 256;

    ash[threadIdx.x] = attn[threadIdx.x];
    __syncthreads();
    const float* hp = h + ((size_t)b * TK_ + z * 256) * N_ + n;
    float acc = 0.f;
    #pragma unroll 8
    for (int tt = 0; tt < 256; tt++)
        acc = fmaf(ash[tt], hp[(size_t)tt * N_], acc);
    g_ct[((size_t)z * B_ + b) * N_ + n] = acc;
}

__global__ __launch_bounds__(256) void ct_reduce_kernel(float* __restrict__ out)
{
    const int i = blockIdx.x * 256 + threadIdx.x;
    float s = 0.f;
    #pragma unroll
    for (int z = 0; z < 8; z++) s += g_ct[(size_t)z * B_ * N_ + i];
    out[i] = s;
}

// ===========================================================================
extern "C" void kernel_launch(void* const* d_in, const int* in_sizes, int n_in,
                              void* d_out, int out_size)
{
    const float* s_t_hat = (const float*)d_in[0];
    const float* h       = (const float*)d_in[1];
    const float* mask    = (const float*)d_in[2];
    const float* cov     = (const float*)d_in[3];
    const float* q_h     = (const float*)d_in[4];
    const float* Wh      = (const float*)d_in[5];
    const float* Wq      = (const float*)d_in[6];
    const float* Wc      = (const float*)d_in[7];
    const float* Wd      = (const float*)d_in[8];
    const float* bd      = (const float*)d_in[9];
    const float* vw      = (const float*)d_in[10];
    float* out = (float*)d_out;

    static bool attr_set = false;
    if (!attr_set) {
        cudaFuncSetAttribute(scores_mma, cudaFuncAttributeMaxDynamicSharedMemorySize, SMEM_TOTAL);
        attr_set = true;
    }

    dec_kernel<<<dim3(32, 128), 256>>>(s_t_hat, Wd, bd);
    scores_mma<<<dim3(NPART, M_ / 128), 256, SMEM_TOTAL>>>(h, q_h, Wh, Wq, Wc, vw, cov);
    softmax_kernel<<<32, 256>>>(mask, cov, out);
    ct_part_kernel<<<dim3(32, N_ / 256, 8), 256>>>(h, out);
    ct_reduce_kernel<<<B_ * N_ / 256, 256>>>(out);
}

// round 5
// speedup vs baseline: 3.0710x; 1.0263x over previous
#include <cuda_runtime.h>
#include <cuda_bf16.h>
#include <math.h>
#include <stdint.h>

#define B_    32
#define TK_   2048
#define N_    1024
#define M_    (B_ * TK_)        // 65536
#define KTOT  2048
#define NPART 8                 // N_/128 column blocks -> score partials

// ---------------- scratch (no allocs allowed) ----------------
__device__ float g_dec[B_ * N_];
__device__ float g_part[NPART * M_];
__device__ float g_ct[8 * B_ * N_];
// pre-converted bf16 hi/lo operands: A = [h|q] over K, B = [Wh|Wq] over K
__device__ __nv_bfloat16 g_Ahi[(size_t)M_ * KTOT];
__device__ __nv_bfloat16 g_Alo[(size_t)M_ * KTOT];
__device__ __nv_bfloat16 g_Bhi[(size_t)N_ * KTOT];
__device__ __nv_bfloat16 g_Blo[(size_t)N_ * KTOT];

// ---------------- smem layout (dynamic) ----------------
// bf16 tiles, row stride 40 elements (80B): conflict-free ldmatrix,
// balanced 16B-slot distribution for cp.async stores
#define A_HI 0
#define A_LO 10240
#define B_HI 20480
#define B_LO 30720
#define STAGE_BYTES 40960
#define NSTAGE 4
#define EPI_DEC (NSTAGE * STAGE_BYTES)     // 163840
#define EPI_WC  (EPI_DEC + 512)
#define EPI_VW  (EPI_WC + 512)
#define EPI_COV (EPI_VW + 512)
#define EPI_RED (EPI_COV + 512)            // 128*16 floats = 8192B
#define SMEM_TOTAL (EPI_RED + 8192)        // 174080

__device__ __forceinline__ uint32_t smem_u32(const void* p) {
    uint32_t a;
    asm("{ .reg .u64 t; cvta.to.shared.u64 t, %1; cvt.u32.u64 %0, t; }" : "=r"(a) : "l"(p));
    return a;
}

#define LDSM_X4(r0, r1, r2, r3, addr) \
    asm volatile("ldmatrix.sync.aligned.m8n8.x4.shared.b16 {%0,%1,%2,%3}, [%4];" \
                 : "=r"(r0), "=r"(r1), "=r"(r2), "=r"(r3) : "r"(addr))
#define MMA16816(d, a, b) \
    asm volatile("mma.sync.aligned.m16n8k16.row.col.f32.bf16.bf16.f32 " \
                 "{%0,%1,%2,%3}, {%4,%5,%6,%7}, {%8,%9}, {%0,%1,%2,%3};" \
                 : "+f"((d)[0]), "+f"((d)[1]), "+f"((d)[2]), "+f"((d)[3]) \
                 : "r"((a)[0]), "r"((a)[1]), "r"((a)[2]), "r"((a)[3]), \
                   "r"((b)[0]), "r"((b)[1]))
#define CP16(smaddr, gptr) \
    asm volatile("cp.async.cg.shared.global [%0], [%1], 16;" \
                 :: "r"(smaddr), "l"(gptr) : "memory")
#define CP_COMMIT() asm volatile("cp.async.commit_group;" ::: "memory")
#define CP_WAIT2()  asm volatile("cp.async.wait_group 2;" ::: "memory")

// fp32x4 -> bf16 hi/lo split
__device__ __forceinline__ void split4(float4 v, uint2& hi, uint2& lo) {
    uint32_t hi01, hi23, lo01, lo23;
    asm("cvt.rn.bf16x2.f32 %0, %1, %2;" : "=r"(hi01) : "f"(v.y), "f"(v.x));
    asm("cvt.rn.bf16x2.f32 %0, %1, %2;" : "=r"(hi23) : "f"(v.w), "f"(v.z));
    float rx = v.x - __uint_as_float(hi01 << 16);
    float ry = v.y - __uint_as_float(hi01 & 0xffff0000u);
    float rz = v.z - __uint_as_float(hi23 << 16);
    float rw = v.w - __uint_as_float(hi23 & 0xffff0000u);
    asm("cvt.rn.bf16x2.f32 %0, %1, %2;" : "=r"(lo01) : "f"(ry), "f"(rx));
    asm("cvt.rn.bf16x2.f32 %0, %1, %2;" : "=r"(lo23) : "f"(rw), "f"(rz));
    hi = make_uint2(hi01, hi23);
    lo = make_uint2(lo01, lo23);
}

// ===========================================================================
// pre-conversion kernels
// ===========================================================================
__global__ __launch_bounds__(256) void conv_a_kernel(
    const float* __restrict__ h, const float* __restrict__ q)
{
    const size_t UN = (size_t)M_ * (N_ / 4);     // float4 units per tensor
    const size_t total = 2 * UN;
    for (size_t u = (size_t)blockIdx.x * 256 + threadIdx.x; u < total;
         u += (size_t)gridDim.x * 256) {
        const int t = (u >= UN) ? 1 : 0;
        const size_t v = u - (t ? UN : 0);
        const size_t m = v >> 8;                 // N_/4 = 256 segs per row
        const int seg = (int)(v & 255);
        float4 val = *(const float4*)((t ? q : h) + m * N_ + seg * 4);
        uint2 hi, lo;
        split4(val, hi, lo);
        size_t d = m * (size_t)KTOT + (size_t)t * N_ + (size_t)seg * 4;
        *(uint2*)(g_Ahi + d) = hi;
        *(uint2*)(g_Alo + d) = lo;
    }
}

__global__ __launch_bounds__(256) void conv_b_kernel(
    const float* __restrict__ Wh, const float* __restrict__ Wq)
{
    const size_t UN = (size_t)N_ * (N_ / 4);     // 262144
    const size_t total = 2 * UN;
    for (size_t u = (size_t)blockIdx.x * 256 + threadIdx.x; u < total;
         u += (size_t)gridDim.x * 256) {
        const int t = (u >= UN) ? 1 : 0;
        const size_t v = u - (t ? UN : 0);
        const size_t n = v >> 8;
        const int seg = (int)(v & 255);
        float4 val = *(const float4*)((t ? Wq : Wh) + n * N_ + seg * 4);
        uint2 hi, lo;
        split4(val, hi, lo);
        size_t d = n * (size_t)KTOT + (size_t)t * N_ + (size_t)seg * 4;
        *(uint2*)(g_Bhi + d) = hi;
        *(uint2*)(g_Blo + d) = lo;
    }
}

// ===========================================================================
// dec_feat[b][m] = s_t_hat[b] . W_d[m] + b_d[m]
// ===========================================================================
__global__ __launch_bounds__(256) void dec_kernel(
    const float* __restrict__ s_t_hat,
    const float* __restrict__ Wd,
    const float* __restrict__ bd)
{
    int b    = blockIdx.x;
    int warp = threadIdx.x >> 5;
    int lane = threadIdx.x & 31;
    int m    = blockIdx.y * 8 + warp;

    const float* sp = s_t_hat + (size_t)b * N_;
    const float* wp = Wd + (size_t)m * N_;
    float acc = 0.f;
    #pragma unroll 4
    for (int k = lane; k < N_; k += 32) acc = fmaf(sp[k], wp[k], acc);
    #pragma unroll
    for (int o = 16; o > 0; o >>= 1) acc += __shfl_xor_sync(0xffffffffu, acc, o);
    if (lane == 0) g_dec[(size_t)b * N_ + m] = acc + bd[m];
}

// ===========================================================================
// scores via bf16 mma.sync (3-term split) on pre-converted operands.
// cp.async 4-stage pipeline. grid (8, 512), 256 threads, 64x32 per warp.
// ===========================================================================
__global__ __launch_bounds__(256, 1) void scores_mma(
    const float* __restrict__ Wc, const float* __restrict__ vw,
    const float* __restrict__ cov)
{
    extern __shared__ char sm[];
    const uint32_t smem = smem_u32(sm);
    const int tid  = threadIdx.x;
    const int lane = tid & 31;
    const int wid  = tid >> 5;
    const int wm   = wid & 1;       // 2 m-groups of 64
    const int wn   = wid >> 1;      // 4 n-groups of 32
    const int mBase = blockIdx.y * 128;
    const int nBase = blockIdx.x * 128;
    const int b     = mBase >> 11;
    const int trow  = mBase & (TK_ - 1);

    float* dec_s = (float*)(sm + EPI_DEC);
    float* wc_s  = (float*)(sm + EPI_WC);
    float* vw_s  = (float*)(sm + EPI_VW);
    float* cov_s = (float*)(sm + EPI_COV);
    float* red   = (float*)(sm + EPI_RED);

    if (tid < 128) {
        dec_s[tid] = g_dec[(size_t)b * N_ + nBase + tid];
        wc_s[tid]  = Wc[nBase + tid];
        vw_s[tid]  = vw[nBase + tid];
        cov_s[tid] = cov[(size_t)b * TK_ + trow + tid];
    }

    // ldmatrix lane-address components
    const int g = lane >> 3;
    const uint32_t a_row = (uint32_t)(((g & 1) << 3) + (lane & 7));
    const uint32_t a_col = (uint32_t)((g >> 1) << 3);
    const uint32_t b4_n  = (uint32_t)((lane >> 4) << 3);        // 0 or 8
    const uint32_t b4_k  = (uint32_t)(((lane >> 3) & 1) << 3);  // 0 or 8
    const uint32_t b4_r  = (uint32_t)(lane & 7);

    // cp.async unit indices: unit u covers row u>>2, 16B-seg u&3
    const int r0 = tid >> 2, s0 = tid & 3;
    const int r1 = (tid + 256) >> 2, s1 = tid & 3;

    float acc[4][4][4];
    #pragma unroll
    for (int mf = 0; mf < 4; mf++)
        #pragma unroll
        for (int nf = 0; nf < 4; nf++)
            #pragma unroll
            for (int x = 0; x < 4; x++) acc[mf][nf][x] = 0.f;

    auto cp_stage = [&](int ks, int st) {
        const uint32_t sbase = smem + st * STAGE_BYTES;
        const int k0 = ks * 32;
        {
            const uint32_t soff = (uint32_t)(r0 * 80 + s0 * 16);
            const size_t ga = (size_t)(mBase + r0) * KTOT + k0 + s0 * 8;
            const size_t gb = (size_t)(nBase + r0) * KTOT + k0 + s0 * 8;
            CP16(sbase + A_HI + soff, g_Ahi + ga);
            CP16(sbase + A_LO + soff, g_Alo + ga);
            CP16(sbase + B_HI + soff, g_Bhi + gb);
            CP16(sbase + B_LO + soff, g_Blo + gb);
        }
        {
            const uint32_t soff = (uint32_t)(r1 * 80 + s1 * 16);
            const size_t ga = (size_t)(mBase + r1) * KTOT + k0 + s1 * 8;
            const size_t gb = (size_t)(nBase + r1) * KTOT + k0 + s1 * 8;
            CP16(sbase + A_HI + soff, g_Ahi + ga);
            CP16(sbase + A_LO + soff, g_Alo + ga);
            CP16(sbase + B_HI + soff, g_Bhi + gb);
            CP16(sbase + B_LO + soff, g_Blo + gb);
        }
    };

    auto mma_step = [&](int st) {
        const uint32_t Ahi = smem + st * STAGE_BYTES + A_HI;
        const uint32_t Alo = smem + st * STAGE_BYTES + A_LO;
        const uint32_t Bhi = smem + st * STAGE_BYTES + B_HI;
        const uint32_t Blo = smem + st * STAGE_BYTES + B_LO;
        #pragma unroll
        for (int kf = 0; kf < 2; kf++) {
            uint32_t ah[4][4], al[4][4], bh[4][2], bl[4][2];
            #pragma unroll
            for (int mf = 0; mf < 4; mf++) {
                uint32_t off = (uint32_t)((wm * 64 + mf * 16 + a_row) * 80 + (kf * 16 + a_col) * 2);
                LDSM_X4(ah[mf][0], ah[mf][1], ah[mf][2], ah[mf][3], Ahi + off);
                LDSM_X4(al[mf][0], al[mf][1], al[mf][2], al[mf][3], Alo + off);
            }
            #pragma unroll
            for (int np = 0; np < 2; np++) {
                uint32_t off = (uint32_t)((wn * 32 + np * 16 + b4_n + b4_r) * 80 + (kf * 16 + b4_k) * 2);
                LDSM_X4(bh[np*2][0], bh[np*2][1], bh[np*2+1][0], bh[np*2+1][1], Bhi + off);
                LDSM_X4(bl[np*2][0], bl[np*2][1], bl[np*2+1][0], bl[np*2+1][1], Blo + off);
            }
            #pragma unroll
            for (int mf = 0; mf < 4; mf++)
                #pragma unroll
                for (int nf = 0; nf < 4; nf++) {
                    MMA16816(acc[mf][nf], ah[mf], bh[nf]);
                    MMA16816(acc[mf][nf], ah[mf], bl[nf]);
                    MMA16816(acc[mf][nf], al[mf], bh[nf]);
                }
        }
    };

    // prologue: fill NSTAGE-1 stages
    #pragma unroll
    for (int p = 0; p < NSTAGE - 1; p++) { cp_stage(p, p); CP_COMMIT(); }

    const int NKS = KTOT / 32;   // 64
    for (int ks = 0; ks < NKS; ks++) {
        CP_WAIT2();
        __syncthreads();
        mma_step(ks & (NSTAGE - 1));
        const int pf = ks + NSTAGE - 1;
        if (pf < NKS) cp_stage(pf, pf & (NSTAGE - 1));
        CP_COMMIT();
    }

    // fused epilogue: tanh + dot with v_w, per-row partials
    #pragma unroll
    for (int mf = 0; mf < 4; mf++) {
        const int rA = wm * 64 + mf * 16 + (lane >> 2);
        const int rB = rA + 8;
        const float covA = cov_s[rA];
        const float covB = cov_s[rB];
        float sA = 0.f, sB = 0.f;
        #pragma unroll
        for (int nf = 0; nf < 4; nf++) {
            const int n0 = wn * 32 + nf * 8 + ((lane & 3) << 1);
            const float d0 = dec_s[n0],   d1 = dec_s[n0 + 1];
            const float w0 = wc_s[n0],    w1 = wc_s[n0 + 1];
            const float v0 = vw_s[n0],    v1 = vw_s[n0 + 1];
            sA += tanhf(acc[mf][nf][0] + d0 + covA * w0) * v0
                + tanhf(acc[mf][nf][1] + d1 + covA * w1) * v1;
            sB += tanhf(acc[mf][nf][2] + d0 + covB * w0) * v0
                + tanhf(acc[mf][nf][3] + d1 + covB * w1) * v1;
        }
        const int colslot = wn * 4 + (lane & 3);
        red[rA * 16 + colslot] = sA;
        red[rB * 16 + colslot] = sB;
    }
    __syncthreads();
    if (tid < 128) {
        float s = 0.f;
        #pragma unroll
        for (int x = 0; x < 16; x++) s += red[tid * 16 + x];
        g_part[(size_t)blockIdx.x * M_ + mBase + tid] = s;
    }
}

// ===========================================================================
// softmax with mask + renormalize; writes attn and coverage_out
// ===========================================================================
__global__ __launch_bounds__(256) void softmax_kernel(
    const float* __restrict__ mask,
    const float* __restrict__ cov,
    float* __restrict__ out)
{
    __shared__ float sh[TK_];
    __shared__ float red[256];
    const int b = blockIdx.x, tid = threadIdx.x;

    float lmax = -1e30f;
    for (int t = tid; t < TK_; t += 256) {
        float s = 0.f;
        #pragma unroll
        for (int c = 0; c < NPART; c++) s += g_part[(size_t)c * M_ + (size_t)b * TK_ + t];
        sh[t] = s;
        lmax = fmaxf(lmax, s);
    }
    red[tid] = lmax; __syncthreads();
    for (int o = 128; o > 0; o >>= 1) {
        if (tid < o) red[tid] = fmaxf(red[tid], red[tid + o]);
        __syncthreads();
    }
    const float mx = red[0];
    __syncthreads();

    float lsum = 0.f;
    for (int t = tid; t < TK_; t += 256) {
        float e = expf(sh[t] - mx) * mask[(size_t)b * TK_ + t];
        sh[t] = e;
        lsum += e;
    }
    red[tid] = lsum; __syncthreads();
    for (int o = 128; o > 0; o >>= 1) {
        if (tid < o) red[tid] += red[tid + o];
        __syncthreads();
    }
    const float inv = 1.f / red[0];

    for (int t = tid; t < TK_; t += 256) {
        float a = sh[t] * inv;
        out[(size_t)B_ * N_ + (size_t)b * TK_ + t] = a;
        out[(size_t)B_ * N_ + (size_t)B_ * TK_ + (size_t)b * TK_ + t] =
            cov[(size_t)b * TK_ + t] + a;
    }
}

// ===========================================================================
// c_t partials over 8 T-chunks, then reduce
// ===========================================================================
__global__ __launch_bounds__(256) void ct_part_kernel(
    const float* __restrict__ h,
    const float* __restrict__ out)
{
    __shared__ float ash[256];
    const int b = blockIdx.x;
    const int n = blockIdx.y * 256 + threadIdx.x;
    const int z = blockIdx.z;
    const float* attn = out + (size_t)B_ * N_ + (size_t)b * TK_ + z * 256;

    ash[threadIdx.x] = attn[threadIdx.x];
    __syncthreads();
    const float* hp = h + ((size_t)b * TK_ + z * 256) * N_ + n;
    float acc = 0.f;
    #pragma unroll 8
    for (int tt = 0; tt < 256; tt++)
        acc = fmaf(ash[tt], hp[(size_t)tt * N_], acc);
    g_ct[((size_t)z * B_ + b) * N_ + n] = acc;
}

__global__ __launch_bounds__(256) void ct_reduce_kernel(float* __restrict__ out)
{
    const int i = blockIdx.x * 256 + threadIdx.x;
    float s = 0.f;
    #pragma unroll
    for (int z = 0; z < 8; z++) s += g_ct[(size_t)z * B_ * N_ + i];
    out[i] = s;
}

// ===========================================================================
extern "C" void kernel_launch(void* const* d_in, const int* in_sizes, int n_in,
                              void* d_out, int out_size)
{
    const float* s_t_hat = (const float*)d_in[0];
    const float* h       = (const float*)d_in[1];
    const float* mask    = (const float*)d_in[2];
    const float* cov     = (const float*)d_in[3];
    const float* q_h     = (const float*)d_in[4];
    const float* Wh      = (const float*)d_in[5];
    const float* Wq      = (const float*)d_in[6];
    const float* Wc      = (const float*)d_in[7];
    const float* Wd      = (const float*)d_in[8];
    const float* bd      = (const float*)d_in[9];
    const float* vw      = (const float*)d_in[10];
    float* out = (float*)d_out;

    static bool attr_set = false;
    if (!attr_set) {
        cudaFuncSetAttribute(scores_mma, cudaFuncAttributeMaxDynamicSharedMemorySize, SMEM_TOTAL);
        attr_set = true;
    }

    conv_a_kernel<<<16384, 256>>>(h, q_h);
    conv_b_kernel<<<2048, 256>>>(Wh, Wq);
    dec_kernel<<<dim3(32, 128), 256>>>(s_t_hat, Wd, bd);
    scores_mma<<<dim3(NPART, M_ / 128), 256, SMEM_TOTAL>>>(Wc, vw, cov);
    softmax_kernel<<<32, 256>>>(mask, cov, out);
    ct_part_kernel<<<dim3(32, N_ / 256, 8), 256>>>(h, out);
    ct_reduce_kernel<<<B_ * N_ / 256, 256>>>(out);
}